// round 4
// baseline (speedup 1.0000x reference)
#include <cuda_runtime.h>

#define NMAX    50000
#define EMAX    800000
#define ETOTMAX (EMAX + NMAX)
#define FEAT    128
#define HEADS   4
#define CH      32
#define NG      64
#define NCLS    10
#define NEG     0.2f
#define NLAYERS 3

// -------- static scratch; 16B-aligned for vector access --------
__device__ __align__(16) float g_xl  [NMAX * FEAT];
__device__ __align__(16) float g_xr  [NMAX * FEAT];
__device__ __align__(16) float g_acc [NMAX * FEAT];     // agg accumulator (init = bias); ELU applied on read
__device__ __align__(16) float g_sc  [ETOTMAX * HEADS];
__device__ __align__(16) float g_max [NMAX * HEADS];
__device__ __align__(16) float g_den [NMAX * HEADS];
__device__ __align__(16) float g_pool[NG * FEAT];
__device__ __align__(16) float g_cnt [NG];

// -------- helpers --------
__device__ __forceinline__ void atomic_max_f(float* addr, float v) {
    int iv = __float_as_int(v);
    if (iv == (int)0x80000000) iv = 0;
    if (iv >= 0) atomicMax((int*)addr, iv);
    else         atomicMin((unsigned int*)addr, (unsigned int)iv);
}

__device__ __forceinline__ void red_add4(float* addr, float a, float b, float c, float d) {
    asm volatile("red.global.add.v4.f32 [%0], {%1, %2, %3, %4};"
                 :: "l"(addr), "f"(a), "f"(b), "f"(c), "f"(d) : "memory");
}

__device__ __forceinline__ float elu_f(float v) { return v > 0.0f ? v : expm1f(v); }

// packed fp32x2 FMA (sm_100+): exact fp32, 2x FFMA throughput
typedef unsigned long long u64;
__device__ __forceinline__ u64 pack2(float x, float y) {
    u64 r; asm("mov.b64 %0, {%1, %2};" : "=l"(r) : "f"(x), "f"(y)); return r;
}
__device__ __forceinline__ void unpack2(u64 v, float& x, float& y) {
    asm("mov.b64 {%0, %1}, %2;" : "=f"(x), "=f"(y) : "l"(v));
}
__device__ __forceinline__ void fma2(u64& d, u64 a, u64 b) {
    asm("fma.rn.f32x2 %0, %1, %2, %0;" : "+l"(d) : "l"(a), "l"(b));
}

// -------- init kernels --------
__global__ void init_acc_k(const float* __restrict__ bias, int n) {
    int i = blockIdx.x * blockDim.x + threadIdx.x;
    if (i < n * FEAT) g_acc[i] = bias[i & (FEAT - 1)];
}
__global__ void init_nh_k(int n) {
    int i = blockIdx.x * blockDim.x + threadIdx.x;
    if (i < n * HEADS) { g_max[i] = __int_as_float(0xff800000); g_den[i] = 0.0f; }
}

// -------- fused GEMM: xl = act@Wl+bl, xr = act@Wr+br --------
// act = x (layer 0) or elu(g_acc) (layers>0; acc is then reset to bias_cur in place).
// Block: 256 threads, 32 rows. Thread (c2 = tid&63 -> col pair, rh = tid>>6 -> 8 rows).
// Inner product uses fma.rn.f32x2 (2 cols packed).
__global__ void gemm_lr_k(const float* __restrict__ x_in, int layer,
                          const float* __restrict__ Wl, const float* __restrict__ Wr,
                          const float* __restrict__ bl, const float* __restrict__ br,
                          const float* __restrict__ bias_cur, int n) {
    __shared__ float xs[32][FEAT + 4];   // stride 132 (mult of 4 -> float4-aligned rows)
    int tid  = threadIdx.x;
    int base = blockIdx.x * 32;

    // cooperative load of 32x128 activations (4 float4 per thread)
    #pragma unroll
    for (int j = 0; j < 4; j++) {
        int idx4 = tid + j * 256;
        int r = idx4 >> 5, c4 = (idx4 & 31) * 4;
        int node = base + r;
        float4 v = make_float4(0.f, 0.f, 0.f, 0.f);
        if (node < n) {
            if (layer == 0) {
                v = *(const float4*)&x_in[node * FEAT + c4];
            } else {
                v = *(const float4*)&g_acc[node * FEAT + c4];
                v.x = elu_f(v.x); v.y = elu_f(v.y); v.z = elu_f(v.z); v.w = elu_f(v.w);
                *(float4*)&g_acc[node * FEAT + c4] = *(const float4*)&bias_cur[c4];
            }
        }
        *(float4*)&xs[r][c4] = v;
    }
    __syncthreads();

    int c2 = tid & 63;        // column pair: cols c2*2, c2*2+1
    int rh = tid >> 6;        // row group: rows rh*8 .. rh*8+7

    const u64* Wl2 = (const u64*)Wl;
    const u64* Wr2 = (const u64*)Wr;

    u64 al[8], ar[8];
    #pragma unroll
    for (int i = 0; i < 8; i++) { al[i] = 0ull; ar[i] = 0ull; }

    #pragma unroll 4
    for (int k = 0; k < FEAT; k++) {
        u64 wl = Wl2[k * 64 + c2];
        u64 wr = Wr2[k * 64 + c2];
        #pragma unroll
        for (int i = 0; i < 8; i++) {
            float xv = xs[rh * 8 + i][k];
            u64 xv2 = pack2(xv, xv);
            fma2(al[i], xv2, wl);
            fma2(ar[i], xv2, wr);
        }
    }

    float bL0 = bl[c2 * 2], bL1 = bl[c2 * 2 + 1];
    float bR0 = br[c2 * 2], bR1 = br[c2 * 2 + 1];
    #pragma unroll
    for (int i = 0; i < 8; i++) {
        int node = base + rh * 8 + i;
        if (node < n) {
            float lo, hi;
            unpack2(al[i], lo, hi);
            *(float2*)&g_xl[node * FEAT + c2 * 2] = make_float2(lo + bL0, hi + bL1);
            unpack2(ar[i], lo, hi);
            *(float2*)&g_xr[node * FEAT + c2 * 2] = make_float2(lo + bR0, hi + bR1);
        }
    }
}

// -------- edge scores: warp per edge, float4 channel loads --------
// channel c = lane*4+j, head = lane>>3; 8-lane-group reduction.
__global__ void edge_score_k(const int* __restrict__ src_a, const int* __restrict__ dst_a,
                             int E, int Etot, const float* __restrict__ att) {
    int wid  = (blockIdx.x * blockDim.x + threadIdx.x) >> 5;
    int lane = threadIdx.x & 31;
    if (wid >= Etot) return;
    int s, d;
    if (wid < E) { s = src_a[wid]; d = dst_a[wid]; }
    else         { s = wid - E; d = s; }

    int c4 = lane * 4;
    float4 a  = *(const float4*)&att [c4];
    float4 vl = *(const float4*)&g_xl[s * FEAT + c4];
    float4 vr = *(const float4*)&g_xr[d * FEAT + c4];

    float z, p = 0.0f;
    z = vl.x + vr.x; p += (z > 0.f ? z : NEG * z) * a.x;
    z = vl.y + vr.y; p += (z > 0.f ? z : NEG * z) * a.y;
    z = vl.z + vr.z; p += (z > 0.f ? z : NEG * z) * a.z;
    z = vl.w + vr.w; p += (z > 0.f ? z : NEG * z) * a.w;

    p += __shfl_xor_sync(0xffffffffu, p, 1);
    p += __shfl_xor_sync(0xffffffffu, p, 2);
    p += __shfl_xor_sync(0xffffffffu, p, 4);

    if ((lane & 7) == 0) {
        int h = lane >> 3;
        g_sc[wid * HEADS + h] = p;
        atomic_max_f(&g_max[d * HEADS + h], p);
    }
}

// -------- exp + denominator: one thread per edge, vectorized --------
__global__ void edge_exp_k(const int* __restrict__ dst_a, int E, int Etot) {
    int e = blockIdx.x * blockDim.x + threadIdx.x;
    if (e >= Etot) return;
    int d = (e < E) ? dst_a[e] : e - E;
    float4 sc = *(const float4*)&g_sc [e * HEADS];
    float4 mx = *(const float4*)&g_max[d * HEADS];
    sc.x = expf(sc.x - mx.x);
    sc.y = expf(sc.y - mx.y);
    sc.z = expf(sc.z - mx.z);
    sc.w = expf(sc.w - mx.w);
    *(float4*)&g_sc[e * HEADS] = sc;
    red_add4(&g_den[d * HEADS], sc.x, sc.y, sc.z, sc.w);
}

__global__ void inv_den_k(int n) {
    int i = blockIdx.x * blockDim.x + threadIdx.x;
    if (i < n * HEADS) g_den[i] = 1.0f / g_den[i];
}

// -------- aggregation: warp per edge; feature = lane*4; alpha via shfl --------
__global__ void edge_agg_k(const int* __restrict__ src_a, const int* __restrict__ dst_a,
                           int E, int Etot) {
    int wid  = (blockIdx.x * blockDim.x + threadIdx.x) >> 5;
    int lane = threadIdx.x & 31;
    if (wid >= Etot) return;
    int s, d;
    if (wid < E) { s = src_a[wid]; d = dst_a[wid]; }
    else         { s = wid - E; d = s; }

    float tmp = 0.0f;
    if (lane < HEADS) tmp = g_sc[wid * HEADS + lane] * g_den[d * HEADS + lane];
    float alpha = __shfl_sync(0xffffffffu, tmp, lane >> 3);

    int c4 = lane * 4;
    const float4 xv = *(const float4*)&g_xl[s * FEAT + c4];
    red_add4(&g_acc[d * FEAT + c4],
             xv.x * alpha, xv.y * alpha, xv.z * alpha, xv.w * alpha);
}

// -------- pooling + classifier --------
__global__ void pool_zero_k() {
    int i = blockIdx.x * blockDim.x + threadIdx.x;
    if (i < NG * FEAT) g_pool[i] = 0.0f;
    if (i < NG)        g_cnt[i]  = 0.0f;
}

__global__ void pool_sum_k(const int* __restrict__ batch, int n) {
    int wid  = (blockIdx.x * blockDim.x + threadIdx.x) >> 5;
    int lane = threadIdx.x & 31;
    if (wid >= n) return;
    int b = batch[wid];
    float4 v = *(const float4*)&g_acc[wid * FEAT + lane * 4];
    v.x = elu_f(v.x); v.y = elu_f(v.y); v.z = elu_f(v.z); v.w = elu_f(v.w);
    red_add4(&g_pool[b * FEAT + lane * 4], v.x, v.y, v.z, v.w);
    if (lane == 0) atomicAdd(&g_cnt[b], 1.0f);
}

__global__ void head_k(const float* __restrict__ lin_w, const float* __restrict__ lin_b,
                       float* __restrict__ out) {
    int g = blockIdx.x;
    int k = threadIdx.x;
    __shared__ float lg[NCLS];
    float inv = 1.0f / fmaxf(g_cnt[g], 1.0f);
    if (k < NCLS) {
        float acc = lin_b[k];
        for (int c = 0; c < FEAT; c++)
            acc = fmaf(g_pool[g * FEAT + c] * inv, lin_w[c * NCLS + k], acc);
        lg[k] = elu_f(acc);
    }
    __syncthreads();
    if (k < NCLS) {
        float m = lg[0];
        #pragma unroll
        for (int j = 1; j < NCLS; j++) m = fmaxf(m, lg[j]);
        float ssum = 0.0f;
        #pragma unroll
        for (int j = 0; j < NCLS; j++) ssum += expf(lg[j] - m);
        out[g * NCLS + k] = lg[k] - m - logf(ssum);
    }
}

// -------- launch --------
extern "C" void kernel_launch(void* const* d_in, const int* in_sizes, int n_in,
                              void* d_out, int out_size) {
    const float* x     = (const float*)d_in[0];
    const int*   ei    = (const int*)d_in[1];
    const int*   batch = (const int*)d_in[2];
    const float* Wl    = (const float*)d_in[3];
    const float* Wr    = (const float*)d_in[4];
    const float* bl    = (const float*)d_in[5];
    const float* br    = (const float*)d_in[6];
    const float* att   = (const float*)d_in[7];
    const float* bias  = (const float*)d_in[8];
    const float* lin_w = (const float*)d_in[9];
    const float* lin_b = (const float*)d_in[10];
    float*       out   = (float*)d_out;

    int E    = in_sizes[1] / 2;
    int n    = in_sizes[0] / FEAT;
    int Etot = E + n;

    const int* src = ei;
    const int* dst = ei + E;

    const int T = 256;
    int g_elem  = (n * FEAT + T - 1) / T;
    int g_edgeW = (int)(((long long)Etot * 32 + T - 1) / T);
    int g_edgeT = (Etot + T - 1) / T;
    int g_nh    = (n * HEADS + T - 1) / T;
    int g_gemm  = (n + 31) / 32;
    int g_poolW = (int)(((long long)n * 32 + T - 1) / T);

    init_acc_k<<<g_elem, T>>>(bias, n);   // acc = bias[0]

    for (int l = 0; l < NLAYERS; l++) {
        init_nh_k<<<g_nh, T>>>(n);
        gemm_lr_k<<<g_gemm, 256>>>(x, l,
                                   Wl + l * FEAT * FEAT, Wr + l * FEAT * FEAT,
                                   bl + l * FEAT, br + l * FEAT,
                                   bias + l * FEAT, n);
        edge_score_k<<<g_edgeW, T>>>(src, dst, E, Etot, att + l * HEADS * CH);
        edge_exp_k<<<g_edgeT, T>>>(dst, E, Etot);
        inv_den_k<<<g_nh, T>>>(n);
        edge_agg_k<<<g_edgeW, T>>>(src, dst, E, Etot);
    }

    pool_zero_k<<<(NG * FEAT + T - 1) / T, T>>>();
    pool_sum_k<<<g_poolW, T>>>(batch, n);
    head_k<<<NG, 32>>>(lin_w, lin_b, out);
}

// round 5
// speedup vs baseline: 1.6945x; 1.6945x over previous
#include <cuda_runtime.h>

#define NMAX    50000
#define EMAX    800000
#define FEAT    128
#define HEADS   4
#define CH      32
#define NG      64
#define NCLS    10
#define NEG     0.2f
#define NLAYERS 3

// -------- static scratch; 16B-aligned for vector access --------
__device__ __align__(16) float g_xl  [NMAX * FEAT];
__device__ __align__(16) float g_xr  [NMAX * FEAT];
__device__ __align__(16) float g_acc [NMAX * FEAT];   // layer output (pre-ELU, bias added)
__device__ __align__(16) float g_pool[NG * FEAT];
__device__ __align__(16) float g_cnt [NG];
// CSR by destination
__device__ int g_cnti    [NMAX];
__device__ int g_cur     [NMAX];
__device__ int g_rowstart[NMAX + 1];
__device__ int g_col     [EMAX];

// -------- helpers --------
__device__ __forceinline__ void red_add4(float* addr, float a, float b, float c, float d) {
    asm volatile("red.global.add.v4.f32 [%0], {%1, %2, %3, %4};"
                 :: "l"(addr), "f"(a), "f"(b), "f"(c), "f"(d) : "memory");
}
__device__ __forceinline__ float elu_f(float v) { return v > 0.0f ? v : expm1f(v); }

// packed fp32x2 FMA (sm_100+)
typedef unsigned long long u64;
__device__ __forceinline__ u64 pack2(float x, float y) {
    u64 r; asm("mov.b64 %0, {%1, %2};" : "=l"(r) : "f"(x), "f"(y)); return r;
}
__device__ __forceinline__ void unpack2(u64 v, float& x, float& y) {
    asm("mov.b64 {%0, %1}, %2;" : "=f"(x), "=f"(y) : "l"(v));
}
__device__ __forceinline__ void fma2(u64& d, u64 a, u64 b) {
    asm("fma.rn.f32x2 %0, %1, %2, %0;" : "+l"(d) : "l"(a), "l"(b));
}

// ================= CSR build (once per launch) =================
__global__ void csr_zero_k(int n) {
    int i = blockIdx.x * blockDim.x + threadIdx.x;
    if (i < n) { g_cnti[i] = 0; g_cur[i] = 0; }
}
__global__ void csr_hist_k(const int* __restrict__ dst, int E) {
    int e = blockIdx.x * blockDim.x + threadIdx.x;
    if (e < E) atomicAdd(&g_cnti[dst[e]], 1);
}
// single-block exclusive scan over n counts (n <= 50176)
__global__ void csr_scan_k(int n) {
    __shared__ int part[1024];
    int t = threadIdx.x;
    int chunk = (n + 1023) / 1024;
    int b = t * chunk, e = min(b + chunk, n);
    int s = 0;
    for (int i = b; i < e; i++) s += g_cnti[i];
    part[t] = s;
    __syncthreads();
    #pragma unroll
    for (int off = 1; off < 1024; off <<= 1) {
        int v = (t >= off) ? part[t - off] : 0;
        __syncthreads();
        part[t] += v;
        __syncthreads();
    }
    int run = part[t] - s;  // exclusive prefix of this chunk
    for (int i = b; i < e; i++) { g_rowstart[i] = run; run += g_cnti[i]; }
    if (e == n && b < n) g_rowstart[n] = run;
    if (n <= b && t == 0) g_rowstart[n] = part[1023]; // safety (unreached for n=50000)
}
__global__ void csr_scatter_k(const int* __restrict__ src, const int* __restrict__ dst, int E) {
    int e = blockIdx.x * blockDim.x + threadIdx.x;
    if (e >= E) return;
    int d = dst[e];
    int p = atomicAdd(&g_cur[d], 1);
    g_col[g_rowstart[d] + p] = src[e];
}

// ================= fused GEMM: xl = act@Wl+bl, xr = act@Wr+br =================
__global__ void gemm_lr_k(const float* __restrict__ x_in, int layer,
                          const float* __restrict__ Wl, const float* __restrict__ Wr,
                          const float* __restrict__ bl, const float* __restrict__ br,
                          int n) {
    __shared__ float xs[32][FEAT + 4];
    int tid  = threadIdx.x;
    int base = blockIdx.x * 32;

    #pragma unroll
    for (int j = 0; j < 4; j++) {
        int idx4 = tid + j * 256;
        int r = idx4 >> 5, c4 = (idx4 & 31) * 4;
        int node = base + r;
        float4 v = make_float4(0.f, 0.f, 0.f, 0.f);
        if (node < n) {
            if (layer == 0) {
                v = *(const float4*)&x_in[node * FEAT + c4];
            } else {
                v = *(const float4*)&g_acc[node * FEAT + c4];
                v.x = elu_f(v.x); v.y = elu_f(v.y); v.z = elu_f(v.z); v.w = elu_f(v.w);
            }
        }
        *(float4*)&xs[r][c4] = v;
    }
    __syncthreads();

    int c2 = tid & 63;
    int rh = tid >> 6;
    const u64* Wl2 = (const u64*)Wl;
    const u64* Wr2 = (const u64*)Wr;

    u64 al[8], ar[8];
    #pragma unroll
    for (int i = 0; i < 8; i++) { al[i] = 0ull; ar[i] = 0ull; }

    #pragma unroll 4
    for (int k = 0; k < FEAT; k++) {
        u64 wl = Wl2[k * 64 + c2];
        u64 wr = Wr2[k * 64 + c2];
        #pragma unroll
        for (int i = 0; i < 8; i++) {
            float xv = xs[rh * 8 + i][k];
            u64 xv2 = pack2(xv, xv);
            fma2(al[i], xv2, wl);
            fma2(ar[i], xv2, wr);
        }
    }

    float bL0 = bl[c2 * 2], bL1 = bl[c2 * 2 + 1];
    float bR0 = br[c2 * 2], bR1 = br[c2 * 2 + 1];
    #pragma unroll
    for (int i = 0; i < 8; i++) {
        int node = base + rh * 8 + i;
        if (node < n) {
            float lo, hi;
            unpack2(al[i], lo, hi);
            *(float2*)&g_xl[node * FEAT + c2 * 2] = make_float2(lo + bL0, hi + bL1);
            unpack2(ar[i], lo, hi);
            *(float2*)&g_xr[node * FEAT + c2 * 2] = make_float2(lo + bR0, hi + bR1);
        }
    }
}

// ================= fused edge pass: warp per destination node =================
// out[d] = sum_{s in N(d)+self} exp(e_sd) * xl[s] / sum exp(e_sd) + bias
// e_sd[h] = att[h] . leaky_relu(xl[s] + xr[d])   (no max-shift: scores are O(1))
__global__ void dst_pass_k(const float* __restrict__ att,
                           const float* __restrict__ bias, int n) {
    int d    = (blockIdx.x * blockDim.x + threadIdx.x) >> 5;
    int lane = threadIdx.x & 31;
    if (d >= n) return;
    int c4 = lane * 4;

    float4 a   = *(const float4*)&att [c4];
    float4 xr4 = *(const float4*)&g_xr[(size_t)d * FEAT + c4];
    float4 xld = *(const float4*)&g_xl[(size_t)d * FEAT + c4];

    // self edge
    float z, p = 0.0f;
    z = xld.x + xr4.x; p += (z > 0.f ? z : NEG * z) * a.x;
    z = xld.y + xr4.y; p += (z > 0.f ? z : NEG * z) * a.y;
    z = xld.z + xr4.z; p += (z > 0.f ? z : NEG * z) * a.z;
    z = xld.w + xr4.w; p += (z > 0.f ? z : NEG * z) * a.w;
    p += __shfl_xor_sync(0xffffffffu, p, 1);
    p += __shfl_xor_sync(0xffffffffu, p, 2);
    p += __shfl_xor_sync(0xffffffffu, p, 4);
    float w = __expf(p) ; // fast exp; refined below
    w = expf(p);
    float4 acc = make_float4(w * xld.x, w * xld.y, w * xld.z, w * xld.w);
    float den = w;

    int beg = g_rowstart[d], end = g_rowstart[d + 1];
    for (int j0 = beg; j0 < end; j0 += 32) {
        int sv = 0;
        if (j0 + lane < end) sv = g_col[j0 + lane];
        int cnt = min(32, end - j0);
        for (int k = 0; k < cnt; k++) {
            int s = __shfl_sync(0xffffffffu, sv, k);
            float4 xl4 = *(const float4*)&g_xl[(size_t)s * FEAT + c4];
            float q = 0.0f;
            z = xl4.x + xr4.x; q += (z > 0.f ? z : NEG * z) * a.x;
            z = xl4.y + xr4.y; q += (z > 0.f ? z : NEG * z) * a.y;
            z = xl4.z + xr4.z; q += (z > 0.f ? z : NEG * z) * a.z;
            z = xl4.w + xr4.w; q += (z > 0.f ? z : NEG * z) * a.w;
            q += __shfl_xor_sync(0xffffffffu, q, 1);
            q += __shfl_xor_sync(0xffffffffu, q, 2);
            q += __shfl_xor_sync(0xffffffffu, q, 4);
            float wj = expf(q);
            acc.x = fmaf(wj, xl4.x, acc.x);
            acc.y = fmaf(wj, xl4.y, acc.y);
            acc.z = fmaf(wj, xl4.z, acc.z);
            acc.w = fmaf(wj, xl4.w, acc.w);
            den += wj;
        }
    }

    float inv = 1.0f / den;
    float4 b4 = *(const float4*)&bias[c4];
    float4 o;
    o.x = fmaf(acc.x, inv, b4.x);
    o.y = fmaf(acc.y, inv, b4.y);
    o.z = fmaf(acc.z, inv, b4.z);
    o.w = fmaf(acc.w, inv, b4.w);
    *(float4*)&g_acc[(size_t)d * FEAT + c4] = o;
}

// ================= pooling + classifier =================
__global__ void pool_zero_k() {
    int i = blockIdx.x * blockDim.x + threadIdx.x;
    if (i < NG * FEAT) g_pool[i] = 0.0f;
    if (i < NG)        g_cnt[i]  = 0.0f;
}

__global__ void pool_sum_k(const int* __restrict__ batch, int n) {
    int wid  = (blockIdx.x * blockDim.x + threadIdx.x) >> 5;
    int lane = threadIdx.x & 31;
    if (wid >= n) return;
    int b = batch[wid];
    float4 v = *(const float4*)&g_acc[(size_t)wid * FEAT + lane * 4];
    v.x = elu_f(v.x); v.y = elu_f(v.y); v.z = elu_f(v.z); v.w = elu_f(v.w);
    red_add4(&g_pool[b * FEAT + lane * 4], v.x, v.y, v.z, v.w);
    if (lane == 0) atomicAdd(&g_cnt[b], 1.0f);
}

__global__ void head_k(const float* __restrict__ lin_w, const float* __restrict__ lin_b,
                       float* __restrict__ out) {
    int g = blockIdx.x;
    int k = threadIdx.x;
    __shared__ float lg[NCLS];
    float inv = 1.0f / fmaxf(g_cnt[g], 1.0f);
    if (k < NCLS) {
        float acc = lin_b[k];
        for (int c = 0; c < FEAT; c++)
            acc = fmaf(g_pool[g * FEAT + c] * inv, lin_w[c * NCLS + k], acc);
        lg[k] = elu_f(acc);
    }
    __syncthreads();
    if (k < NCLS) {
        float m = lg[0];
        #pragma unroll
        for (int j = 1; j < NCLS; j++) m = fmaxf(m, lg[j]);
        float ssum = 0.0f;
        #pragma unroll
        for (int j = 0; j < NCLS; j++) ssum += expf(lg[j] - m);
        out[g * NCLS + k] = lg[k] - m - logf(ssum);
    }
}

// ================= launch =================
extern "C" void kernel_launch(void* const* d_in, const int* in_sizes, int n_in,
                              void* d_out, int out_size) {
    const float* x     = (const float*)d_in[0];
    const int*   ei    = (const int*)d_in[1];
    const int*   batch = (const int*)d_in[2];
    const float* Wl    = (const float*)d_in[3];
    const float* Wr    = (const float*)d_in[4];
    const float* bl    = (const float*)d_in[5];
    const float* br    = (const float*)d_in[6];
    const float* att   = (const float*)d_in[7];
    const float* bias  = (const float*)d_in[8];
    const float* lin_w = (const float*)d_in[9];
    const float* lin_b = (const float*)d_in[10];
    float*       out   = (float*)d_out;

    int E = in_sizes[1] / 2;
    int n = in_sizes[0] / FEAT;

    const int* src = ei;
    const int* dst = ei + E;

    const int T = 256;
    int g_n     = (n + T - 1) / T;
    int g_e     = (E + T - 1) / T;
    int g_gemm  = (n + 31) / 32;
    int g_dstW  = (int)(((long long)n * 32 + T - 1) / T);
    int g_poolW = (int)(((long long)n * 32 + T - 1) / T);

    // CSR build (by destination)
    csr_zero_k<<<g_n, T>>>(n);
    csr_hist_k<<<g_e, T>>>(dst, E);
    csr_scan_k<<<1, 1024>>>(n);
    csr_scatter_k<<<g_e, T>>>(src, dst, E);

    for (int l = 0; l < NLAYERS; l++) {
        gemm_lr_k<<<g_gemm, 256>>>(x, l,
                                   Wl + l * FEAT * FEAT, Wr + l * FEAT * FEAT,
                                   bl + l * FEAT, br + l * FEAT, n);
        dst_pass_k<<<g_dstW, T>>>(att + l * HEADS * CH, bias + l * FEAT, n);
    }

    pool_zero_k<<<(NG * FEAT + T - 1) / T, T>>>();
    pool_sum_k<<<g_poolW, T>>>(batch, n);
    head_k<<<NG, 32>>>(lin_w, lin_b, out);
}

// round 7
// speedup vs baseline: 1.8917x; 1.1164x over previous
#include <cuda_runtime.h>

#define NMAX    50000
#define EMAX    800000
#define FEAT    128
#define HEADS   4
#define CH      32
#define NG      64
#define NCLS    10
#define NEG     0.2f
#define NLAYERS 3

// -------- static scratch; 16B-aligned for vector access --------
__device__ __align__(16) float g_xl  [NMAX * FEAT];
__device__ __align__(16) float g_xr  [NMAX * FEAT];
__device__ __align__(16) float g_acc [NMAX * FEAT];
__device__ __align__(16) float g_pool[NG * FEAT];
__device__ __align__(16) float g_cnt [NG];
// CSR by destination
__device__ int g_cnti    [NMAX];
__device__ int g_cur     [NMAX];
__device__ int g_rowstart[NMAX + 1];
__device__ int g_col     [EMAX];

// -------- helpers --------
__device__ __forceinline__ void red_add4(float* addr, float a, float b, float c, float d) {
    asm volatile("red.global.add.v4.f32 [%0], {%1, %2, %3, %4};"
                 :: "l"(addr), "f"(a), "f"(b), "f"(c), "f"(d) : "memory");
}
__device__ __forceinline__ float elu_f(float v) { return v > 0.0f ? v : expm1f(v); }

typedef unsigned long long u64;
__device__ __forceinline__ u64 pack2(float x, float y) {
    u64 r; asm("mov.b64 %0, {%1, %2};" : "=l"(r) : "f"(x), "f"(y)); return r;
}
__device__ __forceinline__ void unpack2(u64 v, float& x, float& y) {
    asm("mov.b64 {%0, %1}, %2;" : "=f"(x), "=f"(y) : "l"(v));
}
__device__ __forceinline__ void fma2(u64& d, u64 a, u64 b) {
    asm("fma.rn.f32x2 %0, %1, %2, %0;" : "+l"(d) : "l"(a), "l"(b));
}

// ================= CSR build (once per launch) =================
__global__ void csr_zero_k(int n) {
    int i = blockIdx.x * blockDim.x + threadIdx.x;
    if (i < n) { g_cnti[i] = 0; g_cur[i] = 0; }
}
__global__ void csr_hist_k(const int* __restrict__ dst, int E) {
    int e = blockIdx.x * blockDim.x + threadIdx.x;
    if (e < E) atomicAdd(&g_cnti[dst[e]], 1);
}
__global__ void csr_scan_k(int n) {
    __shared__ int part[1024];
    int t = threadIdx.x;
    int chunk = (n + 1023) / 1024;
    int b = t * chunk, e = min(b + chunk, n);
    int s = 0;
    for (int i = b; i < e; i++) s += g_cnti[i];
    part[t] = s;
    __syncthreads();
    #pragma unroll
    for (int off = 1; off < 1024; off <<= 1) {
        int v = (t >= off) ? part[t - off] : 0;
        __syncthreads();
        part[t] += v;
        __syncthreads();
    }
    int run = part[t] - s;
    for (int i = b; i < e; i++) { g_rowstart[i] = run; run += g_cnti[i]; }
    if (e == n && b < n) g_rowstart[n] = run;
}
__global__ void csr_scatter_k(const int* __restrict__ src, const int* __restrict__ dst, int E) {
    int e = blockIdx.x * blockDim.x + threadIdx.x;
    if (e >= E) return;
    int d = dst[e];
    int p = atomicAdd(&g_cur[d], 1);
    g_col[g_rowstart[d] + p] = src[e];
}

// ================= fused GEMM: xl = act@Wl+bl, xr = act@Wr+br =================
__global__ void gemm_lr_k(const float* __restrict__ x_in, int layer,
                          const float* __restrict__ Wl, const float* __restrict__ Wr,
                          const float* __restrict__ bl, const float* __restrict__ br,
                          int n) {
    __shared__ float xs[32][FEAT + 4];
    int tid  = threadIdx.x;
    int base = blockIdx.x * 32;

    #pragma unroll
    for (int j = 0; j < 4; j++) {
        int idx4 = tid + j * 256;
        int r = idx4 >> 5, c4 = (idx4 & 31) * 4;
        int node = base + r;
        float4 v = make_float4(0.f, 0.f, 0.f, 0.f);
        if (node < n) {
            if (layer == 0) {
                v = *(const float4*)&x_in[node * FEAT + c4];
            } else {
                v = *(const float4*)&g_acc[node * FEAT + c4];
                v.x = elu_f(v.x); v.y = elu_f(v.y); v.z = elu_f(v.z); v.w = elu_f(v.w);
            }
        }
        *(float4*)&xs[r][c4] = v;
    }
    __syncthreads();

    int c2 = tid & 63;
    int rh = tid >> 6;
    const u64* Wl2 = (const u64*)Wl;
    const u64* Wr2 = (const u64*)Wr;

    u64 al[8], ar[8];
    #pragma unroll
    for (int i = 0; i < 8; i++) { al[i] = 0ull; ar[i] = 0ull; }

    #pragma unroll 4
    for (int k = 0; k < FEAT; k++) {
        u64 wl = Wl2[k * 64 + c2];
        u64 wr = Wr2[k * 64 + c2];
        #pragma unroll
        for (int i = 0; i < 8; i++) {
            float xv = xs[rh * 8 + i][k];
            u64 xv2 = pack2(xv, xv);
            fma2(al[i], xv2, wl);
            fma2(ar[i], xv2, wr);
        }
    }

    float bL0 = bl[c2 * 2], bL1 = bl[c2 * 2 + 1];
    float bR0 = br[c2 * 2], bR1 = br[c2 * 2 + 1];
    #pragma unroll
    for (int i = 0; i < 8; i++) {
        int node = base + rh * 8 + i;
        if (node < n) {
            float lo, hi;
            unpack2(al[i], lo, hi);
            *(float2*)&g_xl[node * FEAT + c2 * 2] = make_float2(lo + bL0, hi + bL1);
            unpack2(ar[i], lo, hi);
            *(float2*)&g_xr[node * FEAT + c2 * 2] = make_float2(lo + bR0, hi + bR1);
        }
    }
}

// ================= fused edge pass: warp per destination node =================
// POOL=0: write pre-ELU output (+bias) to g_acc.
// POOL=1: apply ELU and reduce into g_pool[batch[d]] (last layer).
template <int POOL>
__global__ void dst_pass_k(const float* __restrict__ att,
                           const float* __restrict__ bias,
                           const int* __restrict__ batch, int n) {
    int d    = (blockIdx.x * blockDim.x + threadIdx.x) >> 5;
    int lane = threadIdx.x & 31;
    if (d >= n) return;
    int c4 = lane * 4;

    float4 a   = *(const float4*)&att [c4];
    float4 xr4 = *(const float4*)&g_xr[(size_t)d * FEAT + c4];
    float4 xld = *(const float4*)&g_xl[(size_t)d * FEAT + c4];

    // self edge
    float z, p = 0.0f;
    z = xld.x + xr4.x; p += (z > 0.f ? z : NEG * z) * a.x;
    z = xld.y + xr4.y; p += (z > 0.f ? z : NEG * z) * a.y;
    z = xld.z + xr4.z; p += (z > 0.f ? z : NEG * z) * a.z;
    z = xld.w + xr4.w; p += (z > 0.f ? z : NEG * z) * a.w;
    p += __shfl_xor_sync(0xffffffffu, p, 1);
    p += __shfl_xor_sync(0xffffffffu, p, 2);
    p += __shfl_xor_sync(0xffffffffu, p, 4);
    float w = __expf(p);
    float4 acc0 = make_float4(w * xld.x, w * xld.y, w * xld.z, w * xld.w);
    float4 acc1 = make_float4(0.f, 0.f, 0.f, 0.f);
    float den0 = w, den1 = 0.0f;

    int beg = g_rowstart[d], end = g_rowstart[d + 1];
    for (int j0 = beg; j0 < end; j0 += 32) {
        int sv = 0;
        if (j0 + lane < end) sv = g_col[j0 + lane];
        int cnt = min(32, end - j0);
        int k = 0;
        // 2 edges per iteration: independent loads + interleaved reduce chains
        for (; k + 1 < cnt; k += 2) {
            int s0 = __shfl_sync(0xffffffffu, sv, k);
            int s1 = __shfl_sync(0xffffffffu, sv, k + 1);
            float4 x0 = *(const float4*)&g_xl[(size_t)s0 * FEAT + c4];
            float4 x1 = *(const float4*)&g_xl[(size_t)s1 * FEAT + c4];
            float q0 = 0.0f, q1 = 0.0f;
            z = x0.x + xr4.x; q0 += (z > 0.f ? z : NEG * z) * a.x;
            z = x1.x + xr4.x; q1 += (z > 0.f ? z : NEG * z) * a.x;
            z = x0.y + xr4.y; q0 += (z > 0.f ? z : NEG * z) * a.y;
            z = x1.y + xr4.y; q1 += (z > 0.f ? z : NEG * z) * a.y;
            z = x0.z + xr4.z; q0 += (z > 0.f ? z : NEG * z) * a.z;
            z = x1.z + xr4.z; q1 += (z > 0.f ? z : NEG * z) * a.z;
            z = x0.w + xr4.w; q0 += (z > 0.f ? z : NEG * z) * a.w;
            z = x1.w + xr4.w; q1 += (z > 0.f ? z : NEG * z) * a.w;
            q0 += __shfl_xor_sync(0xffffffffu, q0, 1);
            q1 += __shfl_xor_sync(0xffffffffu, q1, 1);
            q0 += __shfl_xor_sync(0xffffffffu, q0, 2);
            q1 += __shfl_xor_sync(0xffffffffu, q1, 2);
            q0 += __shfl_xor_sync(0xffffffffu, q0, 4);
            q1 += __shfl_xor_sync(0xffffffffu, q1, 4);
            float w0 = __expf(q0);
            float w1 = __expf(q1);
            acc0.x = fmaf(w0, x0.x, acc0.x); acc1.x = fmaf(w1, x1.x, acc1.x);
            acc0.y = fmaf(w0, x0.y, acc0.y); acc1.y = fmaf(w1, x1.y, acc1.y);
            acc0.z = fmaf(w0, x0.z, acc0.z); acc1.z = fmaf(w1, x1.z, acc1.z);
            acc0.w = fmaf(w0, x0.w, acc0.w); acc1.w = fmaf(w1, x1.w, acc1.w);
            den0 += w0; den1 += w1;
        }
        if (k < cnt) {
            int s0 = __shfl_sync(0xffffffffu, sv, k);
            float4 x0 = *(const float4*)&g_xl[(size_t)s0 * FEAT + c4];
            float q0 = 0.0f;
            z = x0.x + xr4.x; q0 += (z > 0.f ? z : NEG * z) * a.x;
            z = x0.y + xr4.y; q0 += (z > 0.f ? z : NEG * z) * a.y;
            z = x0.z + xr4.z; q0 += (z > 0.f ? z : NEG * z) * a.z;
            z = x0.w + xr4.w; q0 += (z > 0.f ? z : NEG * z) * a.w;
            q0 += __shfl_xor_sync(0xffffffffu, q0, 1);
            q0 += __shfl_xor_sync(0xffffffffu, q0, 2);
            q0 += __shfl_xor_sync(0xffffffffu, q0, 4);
            float w0 = __expf(q0);
            acc0.x = fmaf(w0, x0.x, acc0.x);
            acc0.y = fmaf(w0, x0.y, acc0.y);
            acc0.z = fmaf(w0, x0.z, acc0.z);
            acc0.w = fmaf(w0, x0.w, acc0.w);
            den0 += w0;
        }
    }

    float inv = 1.0f / (den0 + den1);
    float4 b4 = *(const float4*)&bias[c4];
    float4 o;
    o.x = fmaf(acc0.x + acc1.x, inv, b4.x);
    o.y = fmaf(acc0.y + acc1.y, inv, b4.y);
    o.z = fmaf(acc0.z + acc1.z, inv, b4.z);
    o.w = fmaf(acc0.w + acc1.w, inv, b4.w);

    if (POOL) {
        o.x = elu_f(o.x); o.y = elu_f(o.y); o.z = elu_f(o.z); o.w = elu_f(o.w);
        int b = batch[d];
        red_add4(&g_pool[b * FEAT + c4], o.x, o.y, o.z, o.w);
        if (lane == 0) atomicAdd(&g_cnt[b], 1.0f);
    } else {
        *(float4*)&g_acc[(size_t)d * FEAT + c4] = o;
    }
}

// ================= pooling init + classifier =================
__global__ void pool_zero_k() {
    int i = blockIdx.x * blockDim.x + threadIdx.x;
    if (i < NG * FEAT) g_pool[i] = 0.0f;
    if (i < NG)        g_cnt[i]  = 0.0f;
}

__global__ void head_k(const float* __restrict__ lin_w, const float* __restrict__ lin_b,
                       float* __restrict__ out) {
    int g = blockIdx.x;
    int k = threadIdx.x;
    __shared__ float lg[NCLS];
    float inv = 1.0f / fmaxf(g_cnt[g], 1.0f);
    if (k < NCLS) {
        float acc = lin_b[k];
        for (int c = 0; c < FEAT; c++)
            acc = fmaf(g_pool[g * FEAT + c] * inv, lin_w[c * NCLS + k], acc);
        lg[k] = elu_f(acc);
    }
    __syncthreads();
    if (k < NCLS) {
        float m = lg[0];
        #pragma unroll
        for (int j = 1; j < NCLS; j++) m = fmaxf(m, lg[j]);
        float ssum = 0.0f;
        #pragma unroll
        for (int j = 0; j < NCLS; j++) ssum += expf(lg[j] - m);
        out[g * NCLS + k] = lg[k] - m - logf(ssum);
    }
}

// ================= launch =================
extern "C" void kernel_launch(void* const* d_in, const int* in_sizes, int n_in,
                              void* d_out, int out_size) {
    const float* x     = (const float*)d_in[0];
    const int*   ei    = (const int*)d_in[1];
    const int*   batch = (const int*)d_in[2];
    const float* Wl    = (const float*)d_in[3];
    const float* Wr    = (const float*)d_in[4];
    const float* bl    = (const float*)d_in[5];
    const float* br    = (const float*)d_in[6];
    const float* att   = (const float*)d_in[7];
    const float* bias  = (const float*)d_in[8];
    const float* lin_w = (const float*)d_in[9];
    const float* lin_b = (const float*)d_in[10];
    float*       out   = (float*)d_out;

    int E = in_sizes[1] / 2;
    int n = in_sizes[0] / FEAT;

    const int* src = ei;
    const int* dst = ei + E;

    const int T = 256;
    int g_n    = (n + T - 1) / T;
    int g_e    = (E + T - 1) / T;
    int g_gemm = (n + 31) / 32;
    int g_dstW = (int)(((long long)n * 32 + T - 1) / T);

    // CSR build (by destination)
    csr_zero_k<<<g_n, T>>>(n);
    csr_hist_k<<<g_e, T>>>(dst, E);
    csr_scan_k<<<1, 1024>>>(n);
    csr_scatter_k<<<g_e, T>>>(src, dst, E);
    pool_zero_k<<<(NG * FEAT + T - 1) / T, T>>>();

    for (int l = 0; l < NLAYERS; l++) {
        gemm_lr_k<<<g_gemm, 256>>>(x, l,
                                   Wl + l * FEAT * FEAT, Wr + l * FEAT * FEAT,
                                   bl + l * FEAT, br + l * FEAT, n);
        if (l < NLAYERS - 1)
            dst_pass_k<0><<<g_dstW, T>>>(att + l * HEADS * CH, bias + l * FEAT, batch, n);
        else
            dst_pass_k<1><<<g_dstW, T>>>(att + l * HEADS * CH, bias + l * FEAT, batch, n);
    }

    head_k<<<NG, 32>>>(lin_w, lin_b, out);
}

// round 8
// speedup vs baseline: 2.0188x; 1.0672x over previous
#include <cuda_runtime.h>

#define NMAX    50000
#define EMAX    800000
#define FEAT    128
#define HEADS   4
#define CH      32
#define NG      64
#define NCLS    10
#define NEG     0.2f
#define NLAYERS 3

// -------- static scratch; 16B-aligned --------
__device__ __align__(16) float g_xl  [NMAX * FEAT];
__device__ __align__(16) float g_xr  [NMAX * FEAT];
__device__ __align__(16) float g_acc [NMAX * FEAT];
__device__ __align__(16) float g_pool[NG * FEAT];
__device__ __align__(16) float g_cnt [NG];
// CSR by destination
__device__ int g_cnti    [NMAX];
__device__ int g_cur     [NMAX];
__device__ int g_rowstart[NMAX + 1];
__device__ int g_col     [EMAX];

// -------- helpers --------
__device__ __forceinline__ void red_add4(float* addr, float a, float b, float c, float d) {
    asm volatile("red.global.add.v4.f32 [%0], {%1, %2, %3, %4};"
                 :: "l"(addr), "f"(a), "f"(b), "f"(c), "f"(d) : "memory");
}
__device__ __forceinline__ float elu_f(float v) { return v > 0.0f ? v : expm1f(v); }

typedef unsigned long long u64;
__device__ __forceinline__ u64 pack2(float x, float y) {
    u64 r; asm("mov.b64 %0, {%1, %2};" : "=l"(r) : "f"(x), "f"(y)); return r;
}
__device__ __forceinline__ void unpack2(u64 v, float& x, float& y) {
    asm("mov.b64 {%0, %1}, %2;" : "=f"(x), "=f"(y) : "l"(v));
}
__device__ __forceinline__ void fma2(u64& d, u64 a, u64 b) {
    asm("fma.rn.f32x2 %0, %1, %2, %0;" : "+l"(d) : "l"(a), "l"(b));
}

// ================= init + CSR build (once per launch) =================
__global__ void init_all_k(int n) {
    int i = blockIdx.x * blockDim.x + threadIdx.x;
    if (i < n) { g_cnti[i] = 0; g_cur[i] = 0; }
    if (i < NG * FEAT) g_pool[i] = 0.0f;
    if (i < NG)        g_cnt[i]  = 0.0f;
}
__global__ void csr_hist_k(const int* __restrict__ dst, int E) {
    int e = blockIdx.x * blockDim.x + threadIdx.x;
    if (e < E) atomicAdd(&g_cnti[dst[e]], 1);
}
__global__ void csr_scan_k(int n) {
    __shared__ int part[1024];
    int t = threadIdx.x;
    int chunk = (n + 1023) / 1024;
    int b = t * chunk, e = min(b + chunk, n);
    int s = 0;
    for (int i = b; i < e; i++) s += g_cnti[i];
    part[t] = s;
    __syncthreads();
    #pragma unroll
    for (int off = 1; off < 1024; off <<= 1) {
        int v = (t >= off) ? part[t - off] : 0;
        __syncthreads();
        part[t] += v;
        __syncthreads();
    }
    int run = part[t] - s;
    for (int i = b; i < e; i++) { g_rowstart[i] = run; run += g_cnti[i]; }
    if (e == n && b < n) g_rowstart[n] = run;
}
__global__ void csr_scatter_k(const int* __restrict__ src, const int* __restrict__ dst, int E) {
    int e = blockIdx.x * blockDim.x + threadIdx.x;
    if (e >= E) return;
    int d = dst[e];
    int p = atomicAdd(&g_cur[d], 1);
    g_col[g_rowstart[d] + p] = src[e];
}

// ================= fused GEMM: xl = act@Wl+bl, xr = act@Wr+br =================
// 128 threads/block, 32 rows/block. Thread: cols c4..c4+3 (2 colpairs), rows rh*8..rh*8+7.
// Per k: 2 LDG.128 (weights both mats), 8 LDS bcast, 32 fma2.
__global__ void gemm_lr_k(const float* __restrict__ x_in, int layer,
                          const float* __restrict__ Wl, const float* __restrict__ Wr,
                          const float* __restrict__ bl, const float* __restrict__ br,
                          int n) {
    __shared__ float xs[32][FEAT + 4];
    int tid  = threadIdx.x;
    int base = blockIdx.x * 32;

    #pragma unroll
    for (int j = 0; j < 8; j++) {
        int idx4 = tid + j * 128;
        int r = idx4 >> 5, c4l = (idx4 & 31) * 4;
        int node = base + r;
        float4 v = make_float4(0.f, 0.f, 0.f, 0.f);
        if (node < n) {
            if (layer == 0) {
                v = *(const float4*)&x_in[node * FEAT + c4l];
            } else {
                v = *(const float4*)&g_acc[node * FEAT + c4l];
                v.x = elu_f(v.x); v.y = elu_f(v.y); v.z = elu_f(v.z); v.w = elu_f(v.w);
            }
        }
        *(float4*)&xs[r][c4l] = v;
    }
    __syncthreads();

    int cp = tid & 31;        // colpair-pair index: cols cp*4 .. cp*4+3
    int rh = tid >> 5;        // row group: rows rh*8 .. rh*8+7

    const ulonglong2* Wl4 = (const ulonglong2*)Wl;  // [k][32] of ulonglong2 (4 cols)
    const ulonglong2* Wr4 = (const ulonglong2*)Wr;

    u64 aL0[8], aL1[8], aR0[8], aR1[8];
    #pragma unroll
    for (int i = 0; i < 8; i++) { aL0[i]=0ull; aL1[i]=0ull; aR0[i]=0ull; aR1[i]=0ull; }

    #pragma unroll 4
    for (int k = 0; k < FEAT; k++) {
        ulonglong2 wl = Wl4[k * 32 + cp];
        ulonglong2 wr = Wr4[k * 32 + cp];
        #pragma unroll
        for (int i = 0; i < 8; i++) {
            float xv = xs[rh * 8 + i][k];
            u64 xv2 = pack2(xv, xv);
            fma2(aL0[i], xv2, wl.x);
            fma2(aL1[i], xv2, wl.y);
            fma2(aR0[i], xv2, wr.x);
            fma2(aR1[i], xv2, wr.y);
        }
    }

    int c4 = cp * 4;
    float4 bL = *(const float4*)&bl[c4];
    float4 bR = *(const float4*)&br[c4];
    #pragma unroll
    for (int i = 0; i < 8; i++) {
        int node = base + rh * 8 + i;
        if (node < n) {
            float4 o;
            unpack2(aL0[i], o.x, o.y); unpack2(aL1[i], o.z, o.w);
            o.x += bL.x; o.y += bL.y; o.z += bL.z; o.w += bL.w;
            *(float4*)&g_xl[(size_t)node * FEAT + c4] = o;
            unpack2(aR0[i], o.x, o.y); unpack2(aR1[i], o.z, o.w);
            o.x += bR.x; o.y += bR.y; o.z += bR.z; o.w += bR.w;
            *(float4*)&g_xr[(size_t)node * FEAT + c4] = o;
        }
    }
}

// ================= fused edge pass: warp per destination node =================
#define SCORE4(x4, q)  do { \
    float _z; \
    _z = (x4).x + xr4.x; q = fmaf(fmaxf(_z, NEG * _z), a.x, q); \
    _z = (x4).y + xr4.y; q = fmaf(fmaxf(_z, NEG * _z), a.y, q); \
    _z = (x4).z + xr4.z; q = fmaf(fmaxf(_z, NEG * _z), a.z, q); \
    _z = (x4).w + xr4.w; q = fmaf(fmaxf(_z, NEG * _z), a.w, q); \
} while (0)

template <int POOL>
__global__ void dst_pass_k(const float* __restrict__ att,
                           const float* __restrict__ bias,
                           const int* __restrict__ batch, int n) {
    int d    = (blockIdx.x * blockDim.x + threadIdx.x) >> 5;
    int lane = threadIdx.x & 31;
    if (d >= n) return;
    int c4 = lane * 4;

    float4 a   = *(const float4*)&att [c4];
    float4 xr4 = *(const float4*)&g_xr[(size_t)d * FEAT + c4];
    float4 xld = *(const float4*)&g_xl[(size_t)d * FEAT + c4];

    // self edge
    float p = 0.0f;
    SCORE4(xld, p);
    p += __shfl_xor_sync(0xffffffffu, p, 1);
    p += __shfl_xor_sync(0xffffffffu, p, 2);
    p += __shfl_xor_sync(0xffffffffu, p, 4);
    float w = __expf(p);
    float4 acc0 = make_float4(w * xld.x, w * xld.y, w * xld.z, w * xld.w);
    float4 acc1 = make_float4(0.f, 0.f, 0.f, 0.f);
    float4 acc2 = make_float4(0.f, 0.f, 0.f, 0.f);
    float4 acc3 = make_float4(0.f, 0.f, 0.f, 0.f);
    float den0 = w, den1 = 0.f, den2 = 0.f, den3 = 0.f;

    int beg = g_rowstart[d], end = g_rowstart[d + 1];
    for (int j0 = beg; j0 < end; j0 += 32) {
        int sv = 0;
        if (j0 + lane < end) sv = g_col[j0 + lane];
        int cnt = min(32, end - j0);
        int k = 0;
        for (; k + 3 < cnt; k += 4) {
            int s0 = __shfl_sync(0xffffffffu, sv, k);
            int s1 = __shfl_sync(0xffffffffu, sv, k + 1);
            int s2 = __shfl_sync(0xffffffffu, sv, k + 2);
            int s3 = __shfl_sync(0xffffffffu, sv, k + 3);
            float4 x0 = *(const float4*)&g_xl[(size_t)s0 * FEAT + c4];
            float4 x1 = *(const float4*)&g_xl[(size_t)s1 * FEAT + c4];
            float4 x2 = *(const float4*)&g_xl[(size_t)s2 * FEAT + c4];
            float4 x3 = *(const float4*)&g_xl[(size_t)s3 * FEAT + c4];
            float q0 = 0.f, q1 = 0.f, q2 = 0.f, q3 = 0.f;
            SCORE4(x0, q0); SCORE4(x1, q1); SCORE4(x2, q2); SCORE4(x3, q3);
            q0 += __shfl_xor_sync(0xffffffffu, q0, 1);
            q1 += __shfl_xor_sync(0xffffffffu, q1, 1);
            q2 += __shfl_xor_sync(0xffffffffu, q2, 1);
            q3 += __shfl_xor_sync(0xffffffffu, q3, 1);
            q0 += __shfl_xor_sync(0xffffffffu, q0, 2);
            q1 += __shfl_xor_sync(0xffffffffu, q1, 2);
            q2 += __shfl_xor_sync(0xffffffffu, q2, 2);
            q3 += __shfl_xor_sync(0xffffffffu, q3, 2);
            q0 += __shfl_xor_sync(0xffffffffu, q0, 4);
            q1 += __shfl_xor_sync(0xffffffffu, q1, 4);
            q2 += __shfl_xor_sync(0xffffffffu, q2, 4);
            q3 += __shfl_xor_sync(0xffffffffu, q3, 4);
            float w0 = __expf(q0), w1 = __expf(q1), w2 = __expf(q2), w3 = __expf(q3);
            acc0.x = fmaf(w0, x0.x, acc0.x); acc1.x = fmaf(w1, x1.x, acc1.x);
            acc2.x = fmaf(w2, x2.x, acc2.x); acc3.x = fmaf(w3, x3.x, acc3.x);
            acc0.y = fmaf(w0, x0.y, acc0.y); acc1.y = fmaf(w1, x1.y, acc1.y);
            acc2.y = fmaf(w2, x2.y, acc2.y); acc3.y = fmaf(w3, x3.y, acc3.y);
            acc0.z = fmaf(w0, x0.z, acc0.z); acc1.z = fmaf(w1, x1.z, acc1.z);
            acc2.z = fmaf(w2, x2.z, acc2.z); acc3.z = fmaf(w3, x3.z, acc3.z);
            acc0.w = fmaf(w0, x0.w, acc0.w); acc1.w = fmaf(w1, x1.w, acc1.w);
            acc2.w = fmaf(w2, x2.w, acc2.w); acc3.w = fmaf(w3, x3.w, acc3.w);
            den0 += w0; den1 += w1; den2 += w2; den3 += w3;
        }
        for (; k < cnt; k++) {
            int s0 = __shfl_sync(0xffffffffu, sv, k);
            float4 x0 = *(const float4*)&g_xl[(size_t)s0 * FEAT + c4];
            float q0 = 0.f;
            SCORE4(x0, q0);
            q0 += __shfl_xor_sync(0xffffffffu, q0, 1);
            q0 += __shfl_xor_sync(0xffffffffu, q0, 2);
            q0 += __shfl_xor_sync(0xffffffffu, q0, 4);
            float w0 = __expf(q0);
            acc0.x = fmaf(w0, x0.x, acc0.x);
            acc0.y = fmaf(w0, x0.y, acc0.y);
            acc0.z = fmaf(w0, x0.z, acc0.z);
            acc0.w = fmaf(w0, x0.w, acc0.w);
            den0 += w0;
        }
    }

    float inv = 1.0f / ((den0 + den1) + (den2 + den3));
    float4 b4 = *(const float4*)&bias[c4];
    float4 o;
    o.x = fmaf((acc0.x + acc1.x) + (acc2.x + acc3.x), inv, b4.x);
    o.y = fmaf((acc0.y + acc1.y) + (acc2.y + acc3.y), inv, b4.y);
    o.z = fmaf((acc0.z + acc1.z) + (acc2.z + acc3.z), inv, b4.z);
    o.w = fmaf((acc0.w + acc1.w) + (acc2.w + acc3.w), inv, b4.w);

    if (POOL) {
        o.x = elu_f(o.x); o.y = elu_f(o.y); o.z = elu_f(o.z); o.w = elu_f(o.w);
        int b = batch[d];
        red_add4(&g_pool[b * FEAT + c4], o.x, o.y, o.z, o.w);
        if (lane == 0) atomicAdd(&g_cnt[b], 1.0f);
    } else {
        *(float4*)&g_acc[(size_t)d * FEAT + c4] = o;
    }
}

// ================= classifier =================
__global__ void head_k(const float* __restrict__ lin_w, const float* __restrict__ lin_b,
                       float* __restrict__ out) {
    int g = blockIdx.x;
    int k = threadIdx.x;
    __shared__ float lg[NCLS];
    float inv = 1.0f / fmaxf(g_cnt[g], 1.0f);
    if (k < NCLS) {
        float acc = lin_b[k];
        for (int c = 0; c < FEAT; c++)
            acc = fmaf(g_pool[g * FEAT + c] * inv, lin_w[c * NCLS + k], acc);
        lg[k] = elu_f(acc);
    }
    __syncthreads();
    if (k < NCLS) {
        float m = lg[0];
        #pragma unroll
        for (int j = 1; j < NCLS; j++) m = fmaxf(m, lg[j]);
        float ssum = 0.0f;
        #pragma unroll
        for (int j = 0; j < NCLS; j++) ssum += expf(lg[j] - m);
        out[g * NCLS + k] = lg[k] - m - logf(ssum);
    }
}

// ================= launch =================
extern "C" void kernel_launch(void* const* d_in, const int* in_sizes, int n_in,
                              void* d_out, int out_size) {
    const float* x     = (const float*)d_in[0];
    const int*   ei    = (const int*)d_in[1];
    const int*   batch = (const int*)d_in[2];
    const float* Wl    = (const float*)d_in[3];
    const float* Wr    = (const float*)d_in[4];
    const float* bl    = (const float*)d_in[5];
    const float* br    = (const float*)d_in[6];
    const float* att   = (const float*)d_in[7];
    const float* bias  = (const float*)d_in[8];
    const float* lin_w = (const float*)d_in[9];
    const float* lin_b = (const float*)d_in[10];
    float*       out   = (float*)d_out;

    int E = in_sizes[1] / 2;
    int n = in_sizes[0] / FEAT;

    const int* src = ei;
    const int* dst = ei + E;

    const int T = 256;
    int g_n    = (n + T - 1) / T;
    int g_e    = (E + T - 1) / T;
    int g_gemm = (n + 31) / 32;
    int g_dstW = (int)(((long long)n * 32 + T - 1) / T);

    init_all_k<<<g_n, T>>>(n);
    csr_hist_k<<<g_e, T>>>(dst, E);
    csr_scan_k<<<1, 1024>>>(n);
    csr_scatter_k<<<g_e, T>>>(src, dst, E);

    for (int l = 0; l < NLAYERS; l++) {
        gemm_lr_k<<<g_gemm, 128>>>(x, l,
                                   Wl + l * FEAT * FEAT, Wr + l * FEAT * FEAT,
                                   bl + l * FEAT, br + l * FEAT, n);
        if (l < NLAYERS - 1)
            dst_pass_k<0><<<g_dstW, T>>>(att + l * HEADS * CH, bias + l * FEAT, batch, n);
        else
            dst_pass_k<1><<<g_dstW, T>>>(att + l * HEADS * CH, bias + l * FEAT, batch, n);
    }

    head_k<<<NG, 32>>>(lin_w, lin_b, out);
}